// round 14
// baseline (speedup 1.0000x reference)
#include <cuda_runtime.h>
#include <cuda_fp16.h>
#include <math.h>
#include <stdint.h>

// Problem constants
#define E_TOT   1600000
#define NNODES  100000
#define HID     192
#define ND      64
#define NEG     0.01f
#define LN_EPS  1e-5f

#define CTA_THREADS 448
#define CTA_WARPS   14
#define NWITER      (E_TOT / 16)      // 100000 warp-iterations
#define GRID_MAIN   152

// scratch
__device__ float g_ex[E_TOT];
__device__ float g_sum[NNODES];
__device__ uint4 g_mh[E_TOT * 8];    // packed fp16 messages, 16 edges = 128 uint4

// ---- SMEM layout (u32 word offsets) ----------------------------------------
#define W1P_OFF 0          // 5 superblocks x 192 n x 16 words = 15360
#define W2P_OFF 15360      // 6 superblocks x  64 n x 16 words =  6144
#define BIN2_OFF 21504
#define GAM2_OFF 21696
#define BET2_OFF 21888
#define WA2_OFF  22080
#define BM2_OFF  22272
#define ASTAGE_OFF 22336   // per-warp A-fragment stage: 10 kb x 32 lanes x 4 words
#define ASTAGE_WARP 1280
#define STASH_OFF (ASTAGE_OFF + CTA_WARPS * ASTAGE_WARP)     // 40256
#define STASH_WARP 768     // 12 slots x 32 lanes x 2 words (uint2)
#define SMEM_WORDS (STASH_OFF + CTA_WARPS * STASH_WARP)      // 51008
#define SMEM_BYTES (SMEM_WORDS * 4)                          // 204032

__device__ __forceinline__ float leaky(float x) { return x >= 0.f ? x : NEG * x; }

__device__ __forceinline__ uint32_t h2pack(float x, float y) {
    __half2 h = __floats2half2_rn(x, y);
    return *(uint32_t*)&h;
}
__device__ __forceinline__ float2 h2unpack(uint32_t u) {
    return __half22float2(*(__half2*)&u);
}

// D += A(f16 m16k16) * B(f16 k16n8), fp32 accumulate
__device__ __forceinline__ void mma16(float* d, const uint32_t* a, uint32_t b0, uint32_t b1) {
    asm volatile(
        "mma.sync.aligned.m16n8k16.row.col.f32.f16.f16.f32 "
        "{%0,%1,%2,%3}, {%4,%5,%6,%7}, {%8,%9}, {%0,%1,%2,%3};"
        : "+f"(d[0]), "+f"(d[1]), "+f"(d[2]), "+f"(d[3])
        : "r"(a[0]), "r"(a[1]), "r"(a[2]), "r"(a[3]), "r"(b0), "r"(b1));
}

// ---------------------------------------------------------------------------
// Round-11 structure at 14 warps: 16 edges/warp, two N-halves, SMEM A-stage,
// SMEM fp16 mess-stash (was registers — freed 24 regs to fit the 448-thread
// 146-reg ceiling), fp32 epilogue constants, packed fp16 output.
// ---------------------------------------------------------------------------
__global__ __launch_bounds__(CTA_THREADS, 1)
void k_main(const float* __restrict__ x_i,
            const float* __restrict__ x_j,
            const float* __restrict__ ea,
            const float* __restrict__ W_in,
            const float* __restrict__ b_in,
            const float* __restrict__ gam,
            const float* __restrict__ bet,
            const float* __restrict__ W_a,
            const float* __restrict__ b_a,
            const float* __restrict__ W_m,
            const float* __restrict__ b_m,
            const int* __restrict__ col)
{
    extern __shared__ __align__(16) uint32_t sw[];
    float* smf = (float*)sw;
    __half* swh = (__half*)sw;
    const int tid  = threadIdx.x;
    const int warp = tid >> 5;
    const int lane = tid & 31;
    const int g = lane >> 2;
    const int p = lane & 3;

    // ---- stage W_in (fp16 packed, GEMM1 permutation) ------------------------
    for (int i = tid; i < 160 * HID; i += CTA_THREADS) {
        int k = i / HID, n = i % HID;
        int r = k & 15;
        int word = (k >> 5) * 3072 + n * 16 + 4 * (r >> 2)
                 + 2 * ((k >> 4) & 1) + ((r >> 1) & 1);
        swh[(W1P_OFF + word) * 2 + (r & 1)] = __float2half(W_in[i]);
    }
    // ---- stage W_mess (fp16 packed, GEMM2 permutation) ----------------------
    for (int i = tid; i < HID * ND; i += CTA_THREADS) {
        int k = i / ND, n = i % ND;
        int nh = k / 96;
        int c = k - 96 * nh;
        int t = c >> 4, r = c & 15;
        int blkG = 6 * nh + t;
        int word = (blkG >> 1) * 1024 + n * 16 + 4 * ((r & 7) >> 1)
                 + 2 * (blkG & 1) + (r >> 3);
        swh[(W2P_OFF + word) * 2 + (r & 1)] = __float2half(W_m[i]);
    }
    for (int i = tid; i < HID; i += CTA_THREADS) {
        smf[BIN2_OFF + i] = b_in[i];
        smf[GAM2_OFF + i] = gam[i];
        smf[BET2_OFF + i] = bet[i];
        smf[WA2_OFF  + i] = W_a[i];
    }
    for (int i = tid; i < ND; i += CTA_THREADS) smf[BM2_OFF + i] = b_m[i];
    __syncthreads();

    const float b_alpha = b_a[0];
    const float2* bin2 = (const float2*)(smf + BIN2_OFF);
    const float2* gam2 = (const float2*)(smf + GAM2_OFF);
    const float2* bet2 = (const float2*)(smf + BET2_OFF);
    const float2* wa2  = (const float2*)(smf + WA2_OFF);
    const float2* bm2  = (const float2*)(smf + BM2_OFF);
    uint4* astage = (uint4*)(sw + ASTAGE_OFF + warp * ASTAGE_WARP);
    uint2* stash  = (uint2*)(sw + STASH_OFF + warp * STASH_WARP);  // [slot*32+lane]
    const int aidx = g * 4 + p;   // lane slot within a kb group of 32

    for (int wi = blockIdx.x * CTA_WARPS + warp; wi < NWITER;
         wi += gridDim.x * CTA_WARPS) {
        const int e_base = wi * 16;

        float acc2[8][4];
        #pragma unroll
        for (int n2 = 0; n2 < 8; n2++)
            #pragma unroll
            for (int c = 0; c < 4; c++) acc2[n2][c] = 0.f;

        float s0 = 0.f, q0 = 0.f, s1 = 0.f, q1 = 0.f;
        float lg0 = 0.f, lg1 = 0.f;

        #pragma unroll
        for (int nh = 0; nh < 2; nh++) {
            // ================= GEMM1 half: acc1[12][4] ======================
            float acc1[12][4];
            #pragma unroll
            for (int nt = 0; nt < 12; nt++)
                #pragma unroll
                for (int c = 0; c < 4; c++) acc1[nt][c] = 0.f;

            #pragma unroll
            for (int sp = 0; sp < 5; sp++) {
                uint32_t aB0[4], aB1[4];
                if (nh == 0) {
                    const float* src; int off, rl;
                    if (sp < 2)      { src = x_j; rl = 64; off = sp * 32; }
                    else if (sp < 4) { src = x_i; rl = 64; off = (sp - 2) * 32; }
                    else             { src = ea;  rl = 32; off = 0; }
                    const float* base = src + (size_t)e_base * rl + off + 4 * p;
                    const float4 u0 = __ldcs((const float4*)(base + g * rl));
                    const float4 u1 = __ldcs((const float4*)(base + g * rl + 16));
                    const float4 v0 = __ldcs((const float4*)(base + (g + 8) * rl));
                    const float4 v1 = __ldcs((const float4*)(base + (g + 8) * rl + 16));
                    aB0[0] = h2pack(u0.x, u0.y); aB0[1] = h2pack(v0.x, v0.y);
                    aB0[2] = h2pack(u0.z, u0.w); aB0[3] = h2pack(v0.z, v0.w);
                    aB1[0] = h2pack(u1.x, u1.y); aB1[1] = h2pack(v1.x, v1.y);
                    aB1[2] = h2pack(u1.z, u1.w); aB1[3] = h2pack(v1.z, v1.w);
                    // stage for half-1 (same thread re-reads -> no sync needed)
                    astage[(2 * sp) * 32 + aidx]     = make_uint4(aB0[0], aB0[1], aB0[2], aB0[3]);
                    astage[(2 * sp + 1) * 32 + aidx] = make_uint4(aB1[0], aB1[1], aB1[2], aB1[3]);
                } else {
                    uint4 r0 = astage[(2 * sp) * 32 + aidx];
                    uint4 r1 = astage[(2 * sp + 1) * 32 + aidx];
                    aB0[0] = r0.x; aB0[1] = r0.y; aB0[2] = r0.z; aB0[3] = r0.w;
                    aB1[0] = r1.x; aB1[1] = r1.y; aB1[2] = r1.z; aB1[3] = r1.w;
                }
                const uint32_t* wb = sw + W1P_OFF + sp * 3072 + nh * 1536
                                   + g * 16 + 4 * p;
                #pragma unroll
                for (int nt = 0; nt < 12; nt++) {
                    uint4 b = *(const uint4*)(wb + nt * 128);
                    mma16(acc1[nt], aB0, b.x, b.y);
                    mma16(acc1[nt], aB1, b.z, b.w);
                }
            }

            // ================= bias + stats partials ========================
            #pragma unroll
            for (int nt = 0; nt < 12; nt++) {
                float2 bb = bin2[(nh * 12 + nt) * 4 + p];
                acc1[nt][0] += bb.x; acc1[nt][1] += bb.y;
                acc1[nt][2] += bb.x; acc1[nt][3] += bb.y;
                s0 += acc1[nt][0] + acc1[nt][1];
                q0 += acc1[nt][0] * acc1[nt][0] + acc1[nt][1] * acc1[nt][1];
                s1 += acc1[nt][2] + acc1[nt][3];
                q1 += acc1[nt][2] * acc1[nt][2] + acc1[nt][3] * acc1[nt][3];
            }

            if (nh == 0) {
                // stash half-0 mess to per-warp SMEM as fp16 (frees 24 regs)
                #pragma unroll
                for (int nt = 0; nt < 12; nt++) {
                    uint2 s;
                    s.x = h2pack(acc1[nt][0], acc1[nt][1]);
                    s.y = h2pack(acc1[nt][2], acc1[nt][3]);
                    stash[nt * 32 + lane] = s;
                }
            } else {
                s0 += __shfl_xor_sync(0xffffffffu, s0, 1);
                s0 += __shfl_xor_sync(0xffffffffu, s0, 2);
                q0 += __shfl_xor_sync(0xffffffffu, q0, 1);
                q0 += __shfl_xor_sync(0xffffffffu, q0, 2);
                s1 += __shfl_xor_sync(0xffffffffu, s1, 1);
                s1 += __shfl_xor_sync(0xffffffffu, s1, 2);
                q1 += __shfl_xor_sync(0xffffffffu, q1, 1);
                q1 += __shfl_xor_sync(0xffffffffu, q1, 2);
                const float mu0 = s0 * (1.f / HID);
                const float mu1 = s1 * (1.f / HID);
                const float rs0 = rsqrtf(fmaxf(q0 * (1.f / HID) - mu0 * mu0, 0.f) + LN_EPS);
                const float rs1 = rsqrtf(fmaxf(q1 * (1.f / HID) - mu1 * mu1, 0.f) + LN_EPS);

                #pragma unroll
                for (int nt = 0; nt < 12; nt++) {
                    float2 gg = gam2[nt * 4 + p];
                    float2 be = bet2[nt * 4 + p];
                    float2 ww = wa2[nt * 4 + p];
                    uint2 s = stash[nt * 32 + lane];
                    float2 m01 = h2unpack(s.x);
                    float2 m23 = h2unpack(s.y);
                    lg0 += leaky((m01.x - mu0) * rs0 * gg.x + be.x) * ww.x;
                    lg0 += leaky((m01.y - mu0) * rs0 * gg.y + be.y) * ww.y;
                    lg1 += leaky((m23.x - mu1) * rs1 * gg.x + be.x) * ww.x;
                    lg1 += leaky((m23.y - mu1) * rs1 * gg.y + be.y) * ww.y;
                }
                #pragma unroll
                for (int nt = 0; nt < 12; nt++) {
                    float2 gg = gam2[(12 + nt) * 4 + p];
                    float2 be = bet2[(12 + nt) * 4 + p];
                    float2 ww = wa2[(12 + nt) * 4 + p];
                    lg0 += leaky((acc1[nt][0] - mu0) * rs0 * gg.x + be.x) * ww.x;
                    lg0 += leaky((acc1[nt][1] - mu0) * rs0 * gg.y + be.y) * ww.y;
                    lg1 += leaky((acc1[nt][2] - mu1) * rs1 * gg.x + be.x) * ww.x;
                    lg1 += leaky((acc1[nt][3] - mu1) * rs1 * gg.y + be.y) * ww.y;
                }
                lg0 += __shfl_xor_sync(0xffffffffu, lg0, 1);
                lg0 += __shfl_xor_sync(0xffffffffu, lg0, 2);
                lg1 += __shfl_xor_sync(0xffffffffu, lg1, 1);
                lg1 += __shfl_xor_sync(0xffffffffu, lg1, 2);
                if (p == 0) {
                    float ex0 = expf(lg0 + b_alpha);
                    float ex1 = expf(lg1 + b_alpha);
                    g_ex[e_base + g]     = ex0;
                    g_ex[e_base + g + 8] = ex1;
                    atomicAdd(&g_sum[col[e_base + g]],     ex0);
                    atomicAdd(&g_sum[col[e_base + g + 8]], ex1);
                }
            }

            // ================= GEMM2 K-half (accumulate into acc2) ==========
            uint32_t af[6][4];
            #pragma unroll
            for (int t = 0; t < 6; t++) {
                af[t][0] = h2pack(leaky(acc1[2 * t][0]),     leaky(acc1[2 * t][1]));
                af[t][1] = h2pack(leaky(acc1[2 * t][2]),     leaky(acc1[2 * t][3]));
                af[t][2] = h2pack(leaky(acc1[2 * t + 1][0]), leaky(acc1[2 * t + 1][1]));
                af[t][3] = h2pack(leaky(acc1[2 * t + 1][2]), leaky(acc1[2 * t + 1][3]));
            }
            #pragma unroll
            for (int s = 0; s < 3; s++) {
                const uint32_t* wb = sw + W2P_OFF + (3 * nh + s) * 1024
                                   + g * 16 + 4 * p;
                #pragma unroll
                for (int n2 = 0; n2 < 8; n2++) {
                    uint4 b = *(const uint4*)(wb + n2 * 128);
                    mma16(acc2[n2], af[2 * s],     b.x, b.y);
                    mma16(acc2[n2], af[2 * s + 1], b.z, b.w);
                }
            }
        }

        // ========== store packed fp16 output (lane-interleaved, streaming) ===
        #pragma unroll
        for (int c = 0; c < 4; c++) {
            float2 bm0 = bm2[(2 * c) * 4 + p];
            float2 bm1 = bm2[(2 * c + 1) * 4 + p];
            uint4 v;
            v.x = h2pack(acc2[2 * c][0] + bm0.x,     acc2[2 * c][1] + bm0.y);
            v.y = h2pack(acc2[2 * c][2] + bm0.x,     acc2[2 * c][3] + bm0.y);
            v.z = h2pack(acc2[2 * c + 1][0] + bm1.x, acc2[2 * c + 1][1] + bm1.y);
            v.w = h2pack(acc2[2 * c + 1][2] + bm1.x, acc2[2 * c + 1][3] + bm1.y);
            __stcs(&g_mh[(size_t)wi * 128 + c * 32 + lane], v);
        }
    }
}

// ---------------------------------------------------------------------------
__global__ void k_init()
{
    int i = blockIdx.x * blockDim.x + threadIdx.x;
    if (i < NNODES) g_sum[i] = 0.f;
}

// Unpack packed fp16 messages, scale by alpha, write fp32 out.
__global__ void k_scale2(const int* __restrict__ col, float* __restrict__ out)
{
    int wid = (blockIdx.x * blockDim.x + threadIdx.x) >> 5;
    if (wid >= NWITER) return;
    int lane = threadIdx.x & 31;
    int g = lane >> 2, p = lane & 3;
    int e0 = wid * 16 + g;
    int e8 = e0 + 8;
    float a0 = g_ex[e0] / (g_sum[col[e0]] + 1e-16f);
    float a1 = g_ex[e8] / (g_sum[col[e8]] + 1e-16f);
    float* o0 = out + (size_t)e0 * 64;
    float* o8 = out + (size_t)e8 * 64;
    #pragma unroll
    for (int c = 0; c < 4; c++) {
        uint4 v = __ldcs(&g_mh[(size_t)wid * 128 + c * 32 + lane]);
        float2 f;
        f = __half22float2(*(__half2*)&v.x);
        *(float2*)(o0 + 16 * c + 2 * p)     = make_float2(f.x * a0, f.y * a0);
        f = __half22float2(*(__half2*)&v.y);
        *(float2*)(o8 + 16 * c + 2 * p)     = make_float2(f.x * a1, f.y * a1);
        f = __half22float2(*(__half2*)&v.z);
        *(float2*)(o0 + 16 * c + 8 + 2 * p) = make_float2(f.x * a0, f.y * a0);
        f = __half22float2(*(__half2*)&v.w);
        *(float2*)(o8 + 16 * c + 8 + 2 * p) = make_float2(f.x * a1, f.y * a1);
    }
}

// ---------------------------------------------------------------------------
extern "C" void kernel_launch(void* const* d_in, const int* in_sizes, int n_in,
                              void* d_out, int out_size)
{
    const float* x_i  = (const float*)d_in[0];
    const float* x_j  = (const float*)d_in[1];
    const float* ea   = (const float*)d_in[2];
    const float* W_in = (const float*)d_in[3];
    const float* b_in = (const float*)d_in[4];
    const float* gam  = (const float*)d_in[5];
    const float* bet  = (const float*)d_in[6];
    const float* W_a  = (const float*)d_in[7];
    const float* b_a  = (const float*)d_in[8];
    const float* W_m  = (const float*)d_in[9];
    const float* b_m  = (const float*)d_in[10];
    const int*   eidx = (const int*)d_in[11];
    float* out = (float*)d_out;
    const int* col = eidx + E_TOT;

    cudaFuncSetAttribute(k_main, cudaFuncAttributeMaxDynamicSharedMemorySize, SMEM_BYTES);

    k_init<<<(NNODES + 255) / 256, 256>>>();
    k_main<<<GRID_MAIN, CTA_THREADS, SMEM_BYTES>>>(
        x_i, x_j, ea, W_in, b_in, gam, bet, W_a, b_a, W_m, b_m, col);
    k_scale2<<<(NWITER * 32 + 255) / 256, 256>>>(col, out);
}

// round 15
// speedup vs baseline: 1.0931x; 1.0931x over previous
#include <cuda_runtime.h>
#include <cuda_fp16.h>
#include <math.h>
#include <stdint.h>

// Problem constants
#define E_TOT   1600000
#define NNODES  100000
#define HID     192
#define ND      64
#define NEG     0.01f
#define LN_EPS  1e-5f

#define CTA_THREADS 384
#define CTA_WARPS   12
#define NWITER      (E_TOT / 16)      // 100000 warp-iterations
#define GRID_MAIN   152

// scratch
__device__ float g_ex[E_TOT];
__device__ float g_sum[NNODES];
__device__ uint4 g_mh[E_TOT * 8];    // packed fp16 messages, 16 edges = 128 uint4

// ---- SMEM layout (u32 word offsets) ----------------------------------------
#define W1P_OFF 0          // 5 superblocks x 192 n x 16 words = 15360
#define W2P_OFF 15360      // 6 superblocks x  64 n x 16 words =  6144
#define BIN2_OFF 21504
#define GAM2_OFF 21696
#define BET2_OFF 21888
#define WA2_OFF  22080
#define BM2_OFF  22272
#define ASTAGE_OFF 22336   // per-warp A-fragment stage: 10 kb x 32 lanes x 4 words
#define ASTAGE_WARP 1280
#define SMEM_WORDS (ASTAGE_OFF + CTA_WARPS * ASTAGE_WARP)   // 37696
#define SMEM_BYTES (SMEM_WORDS * 4)                          // 150784

__device__ __forceinline__ float leaky(float x) { return x >= 0.f ? x : NEG * x; }

__device__ __forceinline__ uint32_t h2pack(float x, float y) {
    __half2 h = __floats2half2_rn(x, y);
    return *(uint32_t*)&h;
}

// D += A(f16 m16k16) * B(f16 k16n8), fp32 accumulate
__device__ __forceinline__ void mma16(float* d, const uint32_t* a, uint32_t b0, uint32_t b1) {
    asm volatile(
        "mma.sync.aligned.m16n8k16.row.col.f32.f16.f16.f32 "
        "{%0,%1,%2,%3}, {%4,%5,%6,%7}, {%8,%9}, {%0,%1,%2,%3};"
        : "+f"(d[0]), "+f"(d[1]), "+f"(d[2]), "+f"(d[3])
        : "r"(a[0]), "r"(a[1]), "r"(a[2]), "r"(a[3]), "r"(b0), "r"(b1));
}

// ---------------------------------------------------------------------------
// Round-13 structure (12 warps, 16 edges/warp, two N-halves, SMEM A-stage,
// register fp16 stash, fp32 epilogue constants, packed fp16 output), with the
// per-half issue order restructured: GEMM2 MMAs are issued IMMEDIATELY after
// the bias/stats-partials loop (they depend only on leaky(acc1)), and the
// latency-bound stash / shuffle-reduce / logit / atomic tail runs after —
// keeping the tensor pipe fed while shuffle chains drain.
// ---------------------------------------------------------------------------
__global__ __launch_bounds__(CTA_THREADS, 1)
void k_main(const float* __restrict__ x_i,
            const float* __restrict__ x_j,
            const float* __restrict__ ea,
            const float* __restrict__ W_in,
            const float* __restrict__ b_in,
            const float* __restrict__ gam,
            const float* __restrict__ bet,
            const float* __restrict__ W_a,
            const float* __restrict__ b_a,
            const float* __restrict__ W_m,
            const float* __restrict__ b_m,
            const int* __restrict__ col)
{
    extern __shared__ __align__(16) uint32_t sw[];
    float* smf = (float*)sw;
    __half* swh = (__half*)sw;
    const int tid  = threadIdx.x;
    const int warp = tid >> 5;
    const int lane = tid & 31;
    const int g = lane >> 2;
    const int p = lane & 3;

    // ---- stage W_in (fp16 packed, GEMM1 permutation) ------------------------
    for (int i = tid; i < 160 * HID; i += CTA_THREADS) {
        int k = i / HID, n = i % HID;
        int r = k & 15;
        int word = (k >> 5) * 3072 + n * 16 + 4 * (r >> 2)
                 + 2 * ((k >> 4) & 1) + ((r >> 1) & 1);
        swh[(W1P_OFF + word) * 2 + (r & 1)] = __float2half(W_in[i]);
    }
    // ---- stage W_mess (fp16 packed, GEMM2 permutation) ----------------------
    for (int i = tid; i < HID * ND; i += CTA_THREADS) {
        int k = i / ND, n = i % ND;
        int nh = k / 96;
        int c = k - 96 * nh;
        int t = c >> 4, r = c & 15;
        int blkG = 6 * nh + t;
        int word = (blkG >> 1) * 1024 + n * 16 + 4 * ((r & 7) >> 1)
                 + 2 * (blkG & 1) + (r >> 3);
        swh[(W2P_OFF + word) * 2 + (r & 1)] = __float2half(W_m[i]);
    }
    for (int i = tid; i < HID; i += CTA_THREADS) {
        smf[BIN2_OFF + i] = b_in[i];
        smf[GAM2_OFF + i] = gam[i];
        smf[BET2_OFF + i] = bet[i];
        smf[WA2_OFF  + i] = W_a[i];
    }
    for (int i = tid; i < ND; i += CTA_THREADS) smf[BM2_OFF + i] = b_m[i];
    __syncthreads();

    const float b_alpha = b_a[0];
    const float2* bin2 = (const float2*)(smf + BIN2_OFF);
    const float2* gam2 = (const float2*)(smf + GAM2_OFF);
    const float2* bet2 = (const float2*)(smf + BET2_OFF);
    const float2* wa2  = (const float2*)(smf + WA2_OFF);
    const float2* bm2  = (const float2*)(smf + BM2_OFF);
    uint4* astage = (uint4*)(sw + ASTAGE_OFF + warp * ASTAGE_WARP);
    const int aidx = g * 4 + p;   // lane slot within a kb group of 32

    for (int wi = blockIdx.x * CTA_WARPS + warp; wi < NWITER;
         wi += gridDim.x * CTA_WARPS) {
        const int e_base = wi * 16;

        float acc2[8][4];
        #pragma unroll
        for (int n2 = 0; n2 < 8; n2++)
            #pragma unroll
            for (int c = 0; c < 4; c++) acc2[n2][c] = 0.f;

        float s0 = 0.f, q0 = 0.f, s1 = 0.f, q1 = 0.f;
        __half2 stash[24];
        float lg0 = 0.f, lg1 = 0.f;

        #pragma unroll
        for (int nh = 0; nh < 2; nh++) {
            // ================= GEMM1 half: acc1[12][4] ======================
            float acc1[12][4];
            #pragma unroll
            for (int nt = 0; nt < 12; nt++)
                #pragma unroll
                for (int c = 0; c < 4; c++) acc1[nt][c] = 0.f;

            #pragma unroll
            for (int sp = 0; sp < 5; sp++) {
                uint32_t aB0[4], aB1[4];
                if (nh == 0) {
                    const float* src; int off, rl;
                    if (sp < 2)      { src = x_j; rl = 64; off = sp * 32; }
                    else if (sp < 4) { src = x_i; rl = 64; off = (sp - 2) * 32; }
                    else             { src = ea;  rl = 32; off = 0; }
                    const float* base = src + (size_t)e_base * rl + off + 4 * p;
                    const float4 u0 = __ldcs((const float4*)(base + g * rl));
                    const float4 u1 = __ldcs((const float4*)(base + g * rl + 16));
                    const float4 v0 = __ldcs((const float4*)(base + (g + 8) * rl));
                    const float4 v1 = __ldcs((const float4*)(base + (g + 8) * rl + 16));
                    aB0[0] = h2pack(u0.x, u0.y); aB0[1] = h2pack(v0.x, v0.y);
                    aB0[2] = h2pack(u0.z, u0.w); aB0[3] = h2pack(v0.z, v0.w);
                    aB1[0] = h2pack(u1.x, u1.y); aB1[1] = h2pack(v1.x, v1.y);
                    aB1[2] = h2pack(u1.z, u1.w); aB1[3] = h2pack(v1.z, v1.w);
                    // stage for half-1 (same thread re-reads -> no sync needed)
                    astage[(2 * sp) * 32 + aidx]     = make_uint4(aB0[0], aB0[1], aB0[2], aB0[3]);
                    astage[(2 * sp + 1) * 32 + aidx] = make_uint4(aB1[0], aB1[1], aB1[2], aB1[3]);
                } else {
                    uint4 r0 = astage[(2 * sp) * 32 + aidx];
                    uint4 r1 = astage[(2 * sp + 1) * 32 + aidx];
                    aB0[0] = r0.x; aB0[1] = r0.y; aB0[2] = r0.z; aB0[3] = r0.w;
                    aB1[0] = r1.x; aB1[1] = r1.y; aB1[2] = r1.z; aB1[3] = r1.w;
                }
                const uint32_t* wb = sw + W1P_OFF + sp * 3072 + nh * 1536
                                   + g * 16 + 4 * p;
                #pragma unroll
                for (int nt = 0; nt < 12; nt++) {
                    uint4 b = *(const uint4*)(wb + nt * 128);
                    mma16(acc1[nt], aB0, b.x, b.y);
                    mma16(acc1[nt], aB1, b.z, b.w);
                }
            }

            // ================= bias + stats partials ========================
            #pragma unroll
            for (int nt = 0; nt < 12; nt++) {
                float2 bb = bin2[(nh * 12 + nt) * 4 + p];
                acc1[nt][0] += bb.x; acc1[nt][1] += bb.y;
                acc1[nt][2] += bb.x; acc1[nt][3] += bb.y;
                s0 += acc1[nt][0] + acc1[nt][1];
                q0 += acc1[nt][0] * acc1[nt][0] + acc1[nt][1] * acc1[nt][1];
                s1 += acc1[nt][2] + acc1[nt][3];
                q1 += acc1[nt][2] * acc1[nt][2] + acc1[nt][3] * acc1[nt][3];
            }

            // ========== GEMM2 K-half FIRST (tensor work issued early) =======
            {
                uint32_t af[6][4];
                #pragma unroll
                for (int t = 0; t < 6; t++) {
                    af[t][0] = h2pack(leaky(acc1[2 * t][0]),     leaky(acc1[2 * t][1]));
                    af[t][1] = h2pack(leaky(acc1[2 * t][2]),     leaky(acc1[2 * t][3]));
                    af[t][2] = h2pack(leaky(acc1[2 * t + 1][0]), leaky(acc1[2 * t + 1][1]));
                    af[t][3] = h2pack(leaky(acc1[2 * t + 1][2]), leaky(acc1[2 * t + 1][3]));
                }
                #pragma unroll
                for (int s = 0; s < 3; s++) {
                    const uint32_t* wb = sw + W2P_OFF + (3 * nh + s) * 1024
                                       + g * 16 + 4 * p;
                    #pragma unroll
                    for (int n2 = 0; n2 < 8; n2++) {
                        uint4 b = *(const uint4*)(wb + n2 * 128);
                        mma16(acc2[n2], af[2 * s],     b.x, b.y);
                        mma16(acc2[n2], af[2 * s + 1], b.z, b.w);
                    }
                }
            }

            // ========== latency-bound tail (stash / reduce / logit) =========
            if (nh == 0) {
                #pragma unroll
                for (int nt = 0; nt < 12; nt++) {
                    stash[2 * nt]     = __floats2half2_rn(acc1[nt][0], acc1[nt][1]);
                    stash[2 * nt + 1] = __floats2half2_rn(acc1[nt][2], acc1[nt][3]);
                }
            } else {
                s0 += __shfl_xor_sync(0xffffffffu, s0, 1);
                s0 += __shfl_xor_sync(0xffffffffu, s0, 2);
                q0 += __shfl_xor_sync(0xffffffffu, q0, 1);
                q0 += __shfl_xor_sync(0xffffffffu, q0, 2);
                s1 += __shfl_xor_sync(0xffffffffu, s1, 1);
                s1 += __shfl_xor_sync(0xffffffffu, s1, 2);
                q1 += __shfl_xor_sync(0xffffffffu, q1, 1);
                q1 += __shfl_xor_sync(0xffffffffu, q1, 2);
                const float mu0 = s0 * (1.f / HID);
                const float mu1 = s1 * (1.f / HID);
                const float rs0 = rsqrtf(fmaxf(q0 * (1.f / HID) - mu0 * mu0, 0.f) + LN_EPS);
                const float rs1 = rsqrtf(fmaxf(q1 * (1.f / HID) - mu1 * mu1, 0.f) + LN_EPS);

                #pragma unroll
                for (int nt = 0; nt < 12; nt++) {
                    float2 gg = gam2[nt * 4 + p];
                    float2 be = bet2[nt * 4 + p];
                    float2 ww = wa2[nt * 4 + p];
                    float2 m01 = __half22float2(stash[2 * nt]);
                    float2 m23 = __half22float2(stash[2 * nt + 1]);
                    lg0 += leaky((m01.x - mu0) * rs0 * gg.x + be.x) * ww.x;
                    lg0 += leaky((m01.y - mu0) * rs0 * gg.y + be.y) * ww.y;
                    lg1 += leaky((m23.x - mu1) * rs1 * gg.x + be.x) * ww.x;
                    lg1 += leaky((m23.y - mu1) * rs1 * gg.y + be.y) * ww.y;
                }
                #pragma unroll
                for (int nt = 0; nt < 12; nt++) {
                    float2 gg = gam2[(12 + nt) * 4 + p];
                    float2 be = bet2[(12 + nt) * 4 + p];
                    float2 ww = wa2[(12 + nt) * 4 + p];
                    lg0 += leaky((acc1[nt][0] - mu0) * rs0 * gg.x + be.x) * ww.x;
                    lg0 += leaky((acc1[nt][1] - mu0) * rs0 * gg.y + be.y) * ww.y;
                    lg1 += leaky((acc1[nt][2] - mu1) * rs1 * gg.x + be.x) * ww.x;
                    lg1 += leaky((acc1[nt][3] - mu1) * rs1 * gg.y + be.y) * ww.y;
                }
                lg0 += __shfl_xor_sync(0xffffffffu, lg0, 1);
                lg0 += __shfl_xor_sync(0xffffffffu, lg0, 2);
                lg1 += __shfl_xor_sync(0xffffffffu, lg1, 1);
                lg1 += __shfl_xor_sync(0xffffffffu, lg1, 2);
                if (p == 0) {
                    float ex0 = expf(lg0 + b_alpha);
                    float ex1 = expf(lg1 + b_alpha);
                    g_ex[e_base + g]     = ex0;
                    g_ex[e_base + g + 8] = ex1;
                    atomicAdd(&g_sum[col[e_base + g]],     ex0);
                    atomicAdd(&g_sum[col[e_base + g + 8]], ex1);
                }
            }
        }

        // ========== store packed fp16 output (lane-interleaved, streaming) ===
        #pragma unroll
        for (int c = 0; c < 4; c++) {
            float2 bm0 = bm2[(2 * c) * 4 + p];
            float2 bm1 = bm2[(2 * c + 1) * 4 + p];
            uint4 v;
            v.x = h2pack(acc2[2 * c][0] + bm0.x,     acc2[2 * c][1] + bm0.y);
            v.y = h2pack(acc2[2 * c][2] + bm0.x,     acc2[2 * c][3] + bm0.y);
            v.z = h2pack(acc2[2 * c + 1][0] + bm1.x, acc2[2 * c + 1][1] + bm1.y);
            v.w = h2pack(acc2[2 * c + 1][2] + bm1.x, acc2[2 * c + 1][3] + bm1.y);
            __stcs(&g_mh[(size_t)wi * 128 + c * 32 + lane], v);
        }
    }
}

// ---------------------------------------------------------------------------
__global__ void k_init()
{
    int i = blockIdx.x * blockDim.x + threadIdx.x;
    if (i < NNODES) g_sum[i] = 0.f;
}

// Unpack packed fp16 messages, scale by alpha, write fp32 out.
__global__ void k_scale2(const int* __restrict__ col, float* __restrict__ out)
{
    int wid = (blockIdx.x * blockDim.x + threadIdx.x) >> 5;
    if (wid >= NWITER) return;
    int lane = threadIdx.x & 31;
    int g = lane >> 2, p = lane & 3;
    int e0 = wid * 16 + g;
    int e8 = e0 + 8;
    float a0 = g_ex[e0] / (g_sum[col[e0]] + 1e-16f);
    float a1 = g_ex[e8] / (g_sum[col[e8]] + 1e-16f);
    float* o0 = out + (size_t)e0 * 64;
    float* o8 = out + (size_t)e8 * 64;
    #pragma unroll
    for (int c = 0; c < 4; c++) {
        uint4 v = __ldcs(&g_mh[(size_t)wid * 128 + c * 32 + lane]);
        float2 f;
        f = __half22float2(*(__half2*)&v.x);
        *(float2*)(o0 + 16 * c + 2 * p)     = make_float2(f.x * a0, f.y * a0);
        f = __half22float2(*(__half2*)&v.y);
        *(float2*)(o8 + 16 * c + 2 * p)     = make_float2(f.x * a1, f.y * a1);
        f = __half22float2(*(__half2*)&v.z);
        *(float2*)(o0 + 16 * c + 8 + 2 * p) = make_float2(f.x * a0, f.y * a0);
        f = __half22float2(*(__half2*)&v.w);
        *(float2*)(o8 + 16 * c + 8 + 2 * p) = make_float2(f.x * a1, f.y * a1);
    }
}

// ---------------------------------------------------------------------------
extern "C" void kernel_launch(void* const* d_in, const int* in_sizes, int n_in,
                              void* d_out, int out_size)
{
    const float* x_i  = (const float*)d_in[0];
    const float* x_j  = (const float*)d_in[1];
    const float* ea   = (const float*)d_in[2];
    const float* W_in = (const float*)d_in[3];
    const float* b_in = (const float*)d_in[4];
    const float* gam  = (const float*)d_in[5];
    const float* bet  = (const float*)d_in[6];
    const float* W_a  = (const float*)d_in[7];
    const float* b_a  = (const float*)d_in[8];
    const float* W_m  = (const float*)d_in[9];
    const float* b_m  = (const float*)d_in[10];
    const int*   eidx = (const int*)d_in[11];
    float* out = (float*)d_out;
    const int* col = eidx + E_TOT;

    cudaFuncSetAttribute(k_main, cudaFuncAttributeMaxDynamicSharedMemorySize, SMEM_BYTES);

    k_init<<<(NNODES + 255) / 256, 256>>>();
    k_main<<<GRID_MAIN, CTA_THREADS, SMEM_BYTES>>>(
        x_i, x_j, ea, W_in, b_in, gam, bet, W_a, b_a, W_m, b_m, col);
    k_scale2<<<(NWITER * 32 + 255) / 256, 256>>>(col, out);
}